// round 2
// baseline (speedup 1.0000x reference)
#include <cuda_runtime.h>
#include <stdint.h>

// Pre-emphasis IIR: y[i] = x[i] + 0.85*y[i-1]; out[o] = float(clip_int16(32768*y[o+91])),
// out[N-91..N-1] = 0. Output dtype is FLOAT32 (quantized values stored as floats).
// Exploits 0.85^128 ~ 9e-10: every block warms up from zero state 128 samples
// before its tile -> fully parallel, HBM-bound (~256MB traffic).

namespace {
constexpr int   kBlock = 256;
constexpr int   kWpt   = 32;                    // outputs per thread
constexpr int   kTile  = kBlock * kWpt;         // 8192 outputs per block
constexpr int   kSkip  = 91;
constexpr int   kWarm  = 128;                   // IIR warmup length
constexpr float kCoef  = 0.85f;
// staged floats: tile + warmup + slop, multiple of 4
constexpr int   kLogF  = 8324;
constexpr int   kPadF  = kLogF + (kLogF >> 5);  // 8584; pad 1/32 -> conflict-free
// output restage needs 8192 + 256 = 8448 <= kPadF  (reuses same smem buffer)
}

__device__ __forceinline__ int padf(int l) { return l + (l >> 5); }

__global__ __launch_bounds__(kBlock)
void preemph_f32_kernel(const float* __restrict__ x, float* __restrict__ out,
                        int n, int nout)
{
    __shared__ float sm[kPadF];
    const int b = blockIdx.x;
    const int t = threadIdx.x;
    // outputs [b*kTile, ...) need y starting at b*kTile+91; warmup starts 128
    // earlier -> x index b*kTile-37; back off 3 more so window base is 16B-aligned.
    const int xstart = b * kTile - 40;

    // ---- Stage x window into padded smem (coalesced LDG.128, scalar STS) ----
    for (int i = t; i < kLogF / 4; i += kBlock) {
        const int g = xstart + 4 * i;
        float4 v;
        if (g >= 0 && g + 3 < n) {
            v = *reinterpret_cast<const float4*>(x + g);
        } else {
            v.x = (g + 0 >= 0 && g + 0 < n) ? x[g + 0] : 0.0f;
            v.y = (g + 1 >= 0 && g + 1 < n) ? x[g + 1] : 0.0f;
            v.z = (g + 2 >= 0 && g + 2 < n) ? x[g + 2] : 0.0f;
            v.w = (g + 3 >= 0 && g + 3 < n) ? x[g + 3] : 0.0f;
        }
        const int p = 4 * i + (i >> 3);   // == padf(4*i); 4 floats stay contiguous
        sm[p]     = v.x;
        sm[p + 1] = v.y;
        sm[p + 2] = v.z;
        sm[p + 3] = v.w;
    }
    __syncthreads();

    // ---- Per-thread IIR: 128-sample warmup then 32 outputs ----
    // thread t's first output o = b*kTile + t*32 -> x logical offset t*32+3+j
    // (lane stride 33 in padded smem: conflict-free)
    const int lb = t * kWpt + 3;
    float y = 0.0f;
    #pragma unroll
    for (int j = 0; j < kWarm; ++j)
        y = fmaf(kCoef, y, sm[padf(lb + j)]);

    float res[kWpt];
    const int obase = b * kTile + t * kWpt;
    const int olast = n - kSkip;            // outputs at/after this index are 0
    #pragma unroll
    for (int k = 0; k < kWpt; ++k) {
        y = fmaf(kCoef, y, sm[padf(lb + kWarm + k)]);
        float v = fminf(fmaxf(32768.0f * y, -32768.0f), 32767.0f);
        // truncate toward zero == astype(int16) semantics; emit as float
        res[k] = (obase + k < olast) ? truncf(v) : 0.0f;
    }
    __syncthreads();   // all smem input reads done; safe to reuse buffer

    // ---- Restage outputs (writer lane stride 33 -> conflict-free) ----
    #pragma unroll
    for (int k = 0; k < kWpt; ++k)
        sm[t * (kWpt + 1) + k] = res[k];    // == padf(t*32 + k)
    __syncthreads();

    // ---- Coalesced float4 stores to gmem ----
    const int rem = nout - b * kTile;       // outputs owned by this block
    if (rem >= kTile) {
        float4* og4 = reinterpret_cast<float4*>(out + (size_t)b * kTile);
        #pragma unroll
        for (int m = 0; m < kTile / (4 * kBlock); ++m) {   // 8 iterations
            const int lf = 4 * (t + m * kBlock);
            const int p = lf + (lf >> 5);   // contiguous group of 4
            float4 v;
            v.x = sm[p];  v.y = sm[p + 1];  v.z = sm[p + 2];  v.w = sm[p + 3];
            og4[t + m * kBlock] = v;
        }
    } else {
        for (int lf = t; lf < rem; lf += kBlock)
            out[(size_t)b * kTile + lf] = sm[padf(lf)];
    }
}

extern "C" void kernel_launch(void* const* d_in, const int* in_sizes, int n_in,
                              void* d_out, int out_size) {
    const float* x = (const float*)d_in[0];
    float* out = (float*)d_out;
    const int n = in_sizes[0];
    const int grid = (out_size + kTile - 1) / kTile;
    preemph_f32_kernel<<<grid, kBlock>>>(x, out, n, out_size);
}

// round 4
// speedup vs baseline: 1.0981x; 1.0981x over previous
#include <cuda_runtime.h>
#include <stdint.h>

// Pre-emphasis IIR y[i] = x[i] + 0.85*y[i-1]; out[o] = float(clip_int16(32768*y[o+91])),
// out[N-91..] = 0. Block-parallel via decay (0.85^96 ~ 1.7e-7).
// R4: fix R3 build break (powers table must be __device__ constexpr for device use).
// Per-thread warmup (128 redundant LDS) replaced by chunk end-state (B) exchange
// through smem + depth-4 carry and FFMA-imm correction -> 4.4x less L1 traffic.

namespace {
constexpr int   kBlock = 256;
constexpr int   kWpt   = 32;                    // outputs per thread
constexpr int   kTile  = kBlock * kWpt;         // 8192 outputs per block
constexpr int   kSkip  = 91;
constexpr float kCoef  = 0.85f;
constexpr int   kCarry = 4;                     // warmup chunks (128 samples)
// staged floats: kTile + 128 warmup + 3 align slop, rounded to /4 -> 8324
constexpr int   kLogF  = 8324;
constexpr int   kPadF  = kLogF + (kLogF >> 5);  // 8584 (out restage needs 8448 <= this)

struct Pows { float v[33]; };
constexpr Pows makePows() {
    Pows p{}; float r = 1.0f;
    for (int i = 0; i < 33; ++i) { p.v[i] = r; r *= 0.85f; }
    return p;
}
__device__ constexpr Pows kP = makePows();      // device-usable powers table

constexpr float cpow(int k) {
    float r = 1.0f;
    for (int i = 0; i < k; ++i) r *= 0.85f;
    return r;
}
constexpr float c32 = cpow(32);
constexpr float c64 = cpow(64);
constexpr float c96 = cpow(96);
}

__device__ __forceinline__ int padf(int l) { return l + (l >> 5); }

__global__ __launch_bounds__(kBlock)
void preemph_f32_kernel(const float* __restrict__ x, float* __restrict__ out,
                        int n, int nout)
{
    __shared__ float sm[kPadF];
    __shared__ float sB[kBlock + kCarry];       // chunk end-states
    const int b = blockIdx.x;
    const int t = threadIdx.x;
    // window covers x[b*kTile - 37 .. b*kTile + 91 + kTile); base backed off 3
    // more (to b*kTile - 40) for 16B alignment. Logical offset 3 == x index
    // b*kTile - 37 (start of warmup chunk 0).
    const int xstart = b * kTile - 40;

    // ---- Stage window into padded smem (coalesced LDG.128, scalar STS) ----
    for (int i = t; i < kLogF / 4; i += kBlock) {
        const int g = xstart + 4 * i;
        float4 v;
        if (g >= 0 && g + 3 < n) {
            v = *reinterpret_cast<const float4*>(x + g);
        } else {
            v.x = (g + 0 >= 0 && g + 0 < n) ? x[g + 0] : 0.0f;
            v.y = (g + 1 >= 0 && g + 1 < n) ? x[g + 1] : 0.0f;
            v.z = (g + 2 >= 0 && g + 2 < n) ? x[g + 2] : 0.0f;
            v.w = (g + 3 >= 0 && g + 3 < n) ? x[g + 3] : 0.0f;
        }
        const int p = 4 * i + (i >> 3);   // == padf(4*i); group of 4 contiguous
        sm[p]     = v.x;
        sm[p + 1] = v.y;
        sm[p + 2] = v.z;
        sm[p + 3] = v.w;
    }
    __syncthreads();

    // ---- Local scan over own chunk (zero start state); keep results in regs ----
    // thread t owns output chunk index t + kCarry; window offset 3 + (t+kCarry)*32.
    // Lane-to-lane logical stride 32 -> padded stride 33: conflict-free.
    const int lb = (t + kCarry) * kWpt + 3;
    float res[kWpt];
    float y = 0.0f;
    #pragma unroll
    for (int k = 0; k < kWpt; ++k) {
        y = fmaf(kCoef, y, sm[padf(lb + k)]);
        res[k] = y;
    }
    sB[t + kCarry] = y;
    if (t < kCarry) {                      // end-states of the 4 warmup chunks
        float y2 = 0.0f;
        const int wb = t * kWpt + 3;
        #pragma unroll
        for (int k = 0; k < kWpt; ++k)
            y2 = fmaf(kCoef, y2, sm[padf(wb + k)]);
        sB[t] = y2;
    }
    __syncthreads();

    // ---- Depth-4 carry: start state for this chunk ----
    const int mc = t + kCarry;
    float s = sB[mc - 1];
    s = fmaf(c32, sB[mc - 2], s);
    s = fmaf(c64, sB[mc - 3], s);
    s = fmaf(c96, sB[mc - 4], s);

    // ---- Correction (FFMA-imm coefficients) + quantize epilogue ----
    const int obase = b * kTile + t * kWpt;
    const int olast = n - kSkip;            // outputs at/after this index are 0
    #pragma unroll
    for (int k = 0; k < kWpt; ++k) {
        float yk = fmaf(s, kP.v[k + 1], res[k]);
        float v = fminf(fmaxf(32768.0f * yk, -32768.0f), 32767.0f);
        // truncate toward zero == astype(int16) semantics; emit as float
        res[k] = (obase + k < olast) ? truncf(v) : 0.0f;
    }
    __syncthreads();   // all smem input/B reads done; safe to reuse buffer

    // ---- Restage outputs (writer lane stride 33 -> conflict-free) ----
    #pragma unroll
    for (int k = 0; k < kWpt; ++k)
        sm[t * (kWpt + 1) + k] = res[k];    // == padf(t*32 + k)
    __syncthreads();

    // ---- Coalesced float4 stores to gmem ----
    const int rem = nout - b * kTile;       // outputs owned by this block
    if (rem >= kTile) {
        float4* og4 = reinterpret_cast<float4*>(out + (size_t)b * kTile);
        #pragma unroll
        for (int m = 0; m < kTile / (4 * kBlock); ++m) {   // 8 iterations
            const int lf = 4 * (t + m * kBlock);
            const int p = lf + (lf >> 5);   // contiguous group of 4
            float4 v;
            v.x = sm[p];  v.y = sm[p + 1];  v.z = sm[p + 2];  v.w = sm[p + 3];
            og4[t + m * kBlock] = v;
        }
    } else {
        for (int lf = t; lf < rem; lf += kBlock)
            out[(size_t)b * kTile + lf] = sm[padf(lf)];
    }
}

extern "C" void kernel_launch(void* const* d_in, const int* in_sizes, int n_in,
                              void* d_out, int out_size) {
    const float* x = (const float*)d_in[0];
    float* out = (float*)d_out;
    const int n = in_sizes[0];
    const int grid = (out_size + kTile - 1) / kTile;
    preemph_f32_kernel<<<grid, kBlock>>>(x, out, n, out_size);
}

// round 6
// speedup vs baseline: 1.3356x; 1.2163x over previous
#include <cuda_runtime.h>
#include <stdint.h>

// Pre-emphasis IIR y[i] = x[i] + 0.85*y[i-1]; out[o] = float(clip_int16(32768*y[o+91])),
// out[N-91..] = 0. Block-parallel via decay (0.85^96 ~ 1.7e-7).
// R6: fix R5 build break (carry coefficients pre-folded into namespace constexpr).
// kWpt 16 halves res[] regs -> 8 CTAs/SM (100% occ) for the latency-bound profile.

namespace {
constexpr int   kBlock = 256;
constexpr int   kWpt   = 16;                    // outputs per thread
constexpr int   kTile  = kBlock * kWpt;         // 4096 outputs per block
constexpr int   kSkip  = 91;
constexpr float kCoef  = 0.85f;
constexpr int   kCarry = 6;                     // warmup chunks (96 samples)
// window: 3 align slop + 96 warmup + 4096 tile = 4195 -> 4196 (mult of 4)
constexpr int   kLogF  = 4196;
constexpr int   kPadF  = kLogF + (kLogF >> 5);  // 4327 (out restage needs 4224 <= this)

struct Pows { float v[17]; };
constexpr Pows makePows() {
    Pows p{}; float r = 1.0f;
    for (int i = 0; i < 17; ++i) { p.v[i] = r; r *= 0.85f; }
    return p;
}
__device__ constexpr Pows kP = makePows();

constexpr float cpow(int k) {
    float r = 1.0f;
    for (int i = 0; i < k; ++i) r *= 0.85f;
    return r;
}
// pre-folded carry coefficients (host constexpr fn can't be called in device code)
constexpr float c16 = cpow(16);
constexpr float c32 = cpow(32);
constexpr float c48 = cpow(48);
constexpr float c64 = cpow(64);
constexpr float c80 = cpow(80);
}

__device__ __forceinline__ int padf(int l) { return l + (l >> 5); }

__global__ __launch_bounds__(kBlock, 8)
void preemph_f32_kernel(const float* __restrict__ x, float* __restrict__ out,
                        int n, int nout)
{
    __shared__ float sm[kPadF];
    __shared__ float sB[kBlock + kCarry];       // chunk end-states
    const int b = blockIdx.x;
    const int t = threadIdx.x;
    // first needed x index: b*kTile + 91 - 96 = b*kTile - 5; base backed off to
    // b*kTile - 8 for 16B alignment -> warmup chunk 0 starts at logical offset 3.
    const int xstart = b * kTile - 8;

    // ---- Stage window into padded smem (coalesced LDG.128, scalar STS) ----
    for (int i = t; i < kLogF / 4; i += kBlock) {
        const int g = xstart + 4 * i;
        float4 v;
        if (g >= 0 && g + 3 < n) {
            v = *reinterpret_cast<const float4*>(x + g);
        } else {
            v.x = (g + 0 >= 0 && g + 0 < n) ? x[g + 0] : 0.0f;
            v.y = (g + 1 >= 0 && g + 1 < n) ? x[g + 1] : 0.0f;
            v.z = (g + 2 >= 0 && g + 2 < n) ? x[g + 2] : 0.0f;
            v.w = (g + 3 >= 0 && g + 3 < n) ? x[g + 3] : 0.0f;
        }
        const int p = 4 * i + (i >> 3);   // == padf(4*i); group of 4 contiguous
        sm[p]     = v.x;
        sm[p + 1] = v.y;
        sm[p + 2] = v.z;
        sm[p + 3] = v.w;
    }
    __syncthreads();

    // ---- Local scan over own 16-sample chunk (zero start state) ----
    // lane-to-lane banks: (16l + l/2) mod 32 covers all 32 -> conflict-free
    const int lb = (t + kCarry) * kWpt + 3;
    float res[kWpt];
    float y = 0.0f;
    #pragma unroll
    for (int k = 0; k < kWpt; ++k) {
        y = fmaf(kCoef, y, sm[padf(lb + k)]);
        res[k] = y;
    }
    sB[t + kCarry] = y;
    if (t < kCarry) {                      // end-states of the 6 warmup chunks
        float y2 = 0.0f;
        const int wb = t * kWpt + 3;
        #pragma unroll
        for (int k = 0; k < kWpt; ++k)
            y2 = fmaf(kCoef, y2, sm[padf(wb + k)]);
        sB[t] = y2;
    }
    __syncthreads();

    // ---- Depth-6 carry: start state for this chunk ----
    const int mc = t + kCarry;
    float s = sB[mc - 1];
    s = fmaf(c16, sB[mc - 2], s);
    s = fmaf(c32, sB[mc - 3], s);
    s = fmaf(c48, sB[mc - 4], s);
    s = fmaf(c64, sB[mc - 5], s);
    s = fmaf(c80, sB[mc - 6], s);

    // ---- Correction (FFMA-imm coefficients) + quantize epilogue ----
    const int obase = b * kTile + t * kWpt;
    const int olast = n - kSkip;            // outputs at/after this index are 0
    #pragma unroll
    for (int k = 0; k < kWpt; ++k) {
        float yk = fmaf(s, kP.v[k + 1], res[k]);
        float v = fminf(fmaxf(32768.0f * yk, -32768.0f), 32767.0f);
        // truncate toward zero == astype(int16) semantics; emit as float
        res[k] = (obase + k < olast) ? truncf(v) : 0.0f;
    }
    __syncthreads();   // all smem input/B reads done; safe to reuse buffer

    // ---- Restage outputs (conflict-free padded writes) ----
    #pragma unroll
    for (int k = 0; k < kWpt; ++k)
        sm[padf(t * kWpt + k)] = res[k];
    __syncthreads();

    // ---- Coalesced float4 stores to gmem ----
    const int rem = nout - b * kTile;       // outputs owned by this block
    if (rem >= kTile) {
        float4* og4 = reinterpret_cast<float4*>(out + (size_t)b * kTile);
        #pragma unroll
        for (int m = 0; m < kTile / (4 * kBlock); ++m) {   // 4 iterations
            const int lf = 4 * (t + m * kBlock);
            const int p = lf + (lf >> 5);   // contiguous group of 4
            float4 v;
            v.x = sm[p];  v.y = sm[p + 1];  v.z = sm[p + 2];  v.w = sm[p + 3];
            og4[t + m * kBlock] = v;
        }
    } else {
        for (int lf = t; lf < rem; lf += kBlock)
            out[(size_t)b * kTile + lf] = sm[padf(lf)];
    }
}

extern "C" void kernel_launch(void* const* d_in, const int* in_sizes, int n_in,
                              void* d_out, int out_size) {
    const float* x = (const float*)d_in[0];
    float* out = (float*)d_out;
    const int n = in_sizes[0];
    const int grid = (out_size + kTile - 1) / kTile;
    preemph_f32_kernel<<<grid, kBlock>>>(x, out, n, out_size);
}

// round 7
// speedup vs baseline: 1.6593x; 1.2423x over previous
#include <cuda_runtime.h>
#include <stdint.h>

// Pre-emphasis IIR y[i] = x[i] + 0.85*y[i-1]; out[o] = float(clip_int16(32768*y[o+91])),
// out[N-91..] = 0. Block-parallel via decay (0.85^96 ~ 1.7e-7).
// R7: direct per-thread LDG.128 of own 16 samples (no input smem staging), uniform
// warmup threads (7 of 256), single smem pass for the +91-shifted restage, saturating
// cvt.rzi.s16 quantize. ~2.2x fewer instructions, 2 barriers.

namespace {
constexpr int   kBlock = 256;
constexpr int   kChunk = 16;
constexpr int   kWarm  = 7;                     // warmup chunks (112 samples)
constexpr int   kMain  = kBlock - kWarm;        // 249 output chunks
constexpr int   kTile  = kMain * kChunk;        // 3984 outputs per block
constexpr int   kSkip  = 91;
constexpr float kCoef  = 0.85f;
constexpr int   kYLog  = kTile + 5;             // restage buffer logical size
constexpr int   kYPad  = kYLog + (kYLog >> 5) + 4;

struct Pows { float v[17]; };
constexpr Pows makePows() {
    Pows p{}; float r = 1.0f;
    for (int i = 0; i < 17; ++i) { p.v[i] = r; r *= 0.85f; }
    return p;
}
__device__ constexpr Pows kP = makePows();

constexpr float cpow(int k) {
    float r = 1.0f;
    for (int i = 0; i < k; ++i) r *= 0.85f;
    return r;
}
constexpr float c16 = cpow(16);
constexpr float c32 = cpow(32);
constexpr float c48 = cpow(48);
constexpr float c64 = cpow(64);
constexpr float c80 = cpow(80);
}

__device__ __forceinline__ int padf(int l) { return l + (l >> 5); }

// Saturating truncate-toward-zero to int16 range, back to float.
// Exactly matches clip(-32768,32767) + astype(int16) (PTX f32->s16 cvt saturates).
__device__ __forceinline__ float q16(float v) {
    short q; asm("cvt.rzi.s16.f32 %0, %1;" : "=h"(q) : "f"(v));
    float r; asm("cvt.rn.f32.s16 %0, %1;" : "=f"(r) : "h"(q));
    return r;
}

__global__ __launch_bounds__(kBlock, 8)
void preemph_f32_kernel(const float* __restrict__ x, float* __restrict__ out,
                        int n, int nout, int nblocks)
{
    __shared__ float smy[kYPad];    // final quantized y, indexed by block-local output pos
    __shared__ float sB[kBlock];    // chunk end-states
    const int b = blockIdx.x;
    const int t = threadIdx.x;
    const bool edge = (b == 0) || (b == nblocks - 1);

    // Every thread (warmup t<7 and main t>=7) scans x[g0 .. g0+16),
    // g0 = b*kTile - 16 + 16*t  (16B-aligned). Inputs pre-scaled by 32768.
    const int g0 = b * kTile - 16 + 16 * t;
    float v[kChunk];
    if (!edge) {
        #pragma unroll
        for (int m = 0; m < 4; ++m) {
            float4 u = *reinterpret_cast<const float4*>(x + g0 + 4 * m);
            v[4 * m + 0] = 32768.0f * u.x;
            v[4 * m + 1] = 32768.0f * u.y;
            v[4 * m + 2] = 32768.0f * u.z;
            v[4 * m + 3] = 32768.0f * u.w;
        }
    } else {
        #pragma unroll
        for (int k = 0; k < kChunk; ++k) {
            const int g = g0 + k;
            v[k] = (g >= 0 && g < n) ? 32768.0f * x[g] : 0.0f;
        }
    }

    // Local scan from zero state; in-place results; end-state to sB.
    float y = 0.0f;
    #pragma unroll
    for (int k = 0; k < kChunk; ++k) {
        y = fmaf(kCoef, y, v[k]);
        v[k] = y;
    }
    sB[t] = y;
    __syncthreads();

    // Depth-6 carry (uniform formula), correct, quantize, restage shifted by the
    // +91 skip so readers get aligned 16-float output chunks.
    // main chunk c = t-7 covers block-local outputs [16c+5, 16c+21);
    // thread 6 (warmup chunk -1) contributes outputs [0,5) via its k=11..15.
    if (t >= 7) {
        float s = sB[t - 1];
        s = fmaf(c16, sB[t - 2], s);
        s = fmaf(c32, sB[t - 3], s);
        s = fmaf(c48, sB[t - 4], s);
        s = fmaf(c64, sB[t - 5], s);
        s = fmaf(c80, sB[t - 6], s);
        const int base = 16 * t - 107;       // = 16*(t-7) + 5
        #pragma unroll
        for (int k = 0; k < kChunk; ++k)
            smy[padf(base + k)] = q16(fmaf(s, kP.v[k + 1], v[k]));
    } else if (t == 6) {
        float s = sB[5];
        s = fmaf(c16, sB[4], s);
        s = fmaf(c32, sB[3], s);
        s = fmaf(c48, sB[2], s);
        s = fmaf(c64, sB[1], s);
        s = fmaf(c80, sB[0], s);
        #pragma unroll
        for (int k = 11; k < kChunk; ++k)
            smy[padf(k - 11)] = q16(fmaf(s, kP.v[k + 1], v[k]));
    }
    __syncthreads();

    // ---- Coalesced stores ----
    const int obase = b * kTile;
    if (!edge) {
        float4* o4 = reinterpret_cast<float4*>(out + obase);
        #pragma unroll
        for (int m = 0; m < 4; ++m) {
            const int lf4 = t + m * kBlock;
            if (lf4 < kTile / 4) {
                const int p = padf(4 * lf4);  // group of 4 contiguous in padded space
                float4 u;
                u.x = smy[p]; u.y = smy[p + 1]; u.z = smy[p + 2]; u.w = smy[p + 3];
                o4[lf4] = u;
            }
        }
    } else {
        const int rem = min(kTile, nout - obase);
        const int zfrom = (n - kSkip) - obase;   // outputs at/after this are 0
        for (int i = t; i < rem; i += kBlock)
            out[obase + i] = (i < zfrom) ? smy[padf(i)] : 0.0f;
    }
}

extern "C" void kernel_launch(void* const* d_in, const int* in_sizes, int n_in,
                              void* d_out, int out_size) {
    const float* x = (const float*)d_in[0];
    float* out = (float*)d_out;
    const int n = in_sizes[0];
    const int grid = (out_size + kTile - 1) / kTile;
    preemph_f32_kernel<<<grid, kBlock>>>(x, out, n, out_size, grid);
}